// round 10
// baseline (speedup 1.0000x reference)
#include <cuda_runtime.h>
#include <cstdint>

#define FNUM 64
#define DEG 16
#define KDEG 5
#define R 4   // rows (batch elements) in flight per warp

// ---------------------------------------------------------------------------
// Packed f32x2 helpers (Blackwell fma.rn.f32x2 — PTX only, ptxas won't fuse)
// ---------------------------------------------------------------------------
typedef unsigned long long u64;

__device__ __forceinline__ u64 pk2(float a, float b) {
    u64 r; asm("mov.b64 %0,{%1,%2};" : "=l"(r) : "f"(a), "f"(b)); return r;
}
__device__ __forceinline__ float2 unpk2(u64 v) {
    float2 r; asm("mov.b64 {%0,%1},%2;" : "=f"(r.x), "=f"(r.y) : "l"(v)); return r;
}
__device__ __forceinline__ u64 ffma2(u64 a, u64 b, u64 c) {
    u64 d; asm("fma.rn.f32x2 %0,%1,%2,%3;" : "=l"(d) : "l"(a), "l"(b), "l"(c)); return d;
}
__device__ __forceinline__ u64 fadd2(u64 a, u64 b) {
    u64 d; asm("add.rn.f32x2 %0,%1,%2;" : "=l"(d) : "l"(a), "l"(b)); return d;
}
__device__ __forceinline__ u64 fmul2(u64 a, u64 b) {
    u64 d; asm("mul.rn.f32x2 %0,%1,%2;" : "=l"(d) : "l"(a), "l"(b)); return d;
}

#define SGN_  0x8000000080000000ULL  // packed sign-flip mask
#define MONE_ 0xBF800000BF800000ULL  // packed (-1.0f, -1.0f)

// Compute R row results s[] from packed inputs cx[] using register-cached
// packed parameters W (LCU, sign-folded+normalized) and C (KAN, sign-folded).
__device__ __forceinline__ void body(const float2* cx, const u64* W, const u64* C,
                                     float* s) {
    u64 x2[R], nx2[R], um1[R], u[R], acc[R];
    // ---- QSVT/LCU: sum_k w'_k * sigma_k T_k(x), k = 1..16 ----
#pragma unroll
    for (int r = 0; r < R; r++) {
        u64 x  = pk2(cx[r].x, cx[r].y);
        x2[r]  = fadd2(x, x);
        nx2[r] = x2[r] ^ SGN_;
        um1[r] = x;                        // u1 = T1
        acc[r] = fmul2(W[0], x);
        u[r]   = ffma2(x2[r], x, MONE_);   // u2 = T2
        acc[r] = ffma2(W[1], u[r], acc[r]);
    }
#pragma unroll
    for (int k = 3; k <= DEG; k++) {
#pragma unroll
        for (int r = 0; r < R; r++) {
            u64 un = ffma2((k & 1) ? nx2[r] : x2[r], u[r], um1[r]);
            acc[r] = ffma2(W[k - 1], un, acc[r]);
            um1[r] = u[r]; u[r] = un;
        }
    }

    // ---- tanh: z = 1 - 2/(e^{2f}+1); |feat| <= 1 so always accurate ----
    u64 z[R];
#pragma unroll
    for (int r = 0; r < R; r++) {
        float2 fe = unpk2(acc[r]);
        float e0 = __expf(2.f * fe.x);
        float e1 = __expf(2.f * fe.y);
        float z0 = 1.f - __fdividef(2.f, e0 + 1.f);
        float z1 = 1.f - __fdividef(2.f, e1 + 1.f);
        z[r] = pk2(z0, z1);
    }

    // ---- KAN: sum_j c'_j * sigma_j T_j(z), j = 0..5 ----
    u64 kacc[R];
#pragma unroll
    for (int r = 0; r < R; r++) {
        x2[r]  = fadd2(z[r], z[r]);
        nx2[r] = x2[r] ^ SGN_;
        um1[r] = z[r];
        kacc[r] = ffma2(C[1], z[r], C[0]);
        u[r]   = ffma2(x2[r], z[r], MONE_);  // T2
        kacc[r] = ffma2(C[2], u[r], kacc[r]);
    }
#pragma unroll
    for (int j = 3; j <= KDEG; j++) {
#pragma unroll
        for (int r = 0; r < R; r++) {
            u64 un = ffma2((j & 1) ? nx2[r] : x2[r], u[r], um1[r]);
            kacc[r] = ffma2(C[j], un, kacc[r]);
            um1[r] = u[r]; u[r] = un;
        }
    }

    // ---- reduce 64 features: 2 per lane + 5-level butterfly (R-wide) ----
#pragma unroll
    for (int r = 0; r < R; r++) {
        float2 pr = unpk2(kacc[r]);
        s[r] = pr.x + pr.y;
    }
#pragma unroll
    for (int o = 16; o; o >>= 1)
#pragma unroll
        for (int r = 0; r < R; r++)
            s[r] += __shfl_xor_sync(0xffffffffu, s[r], o);
}

// ---------------------------------------------------------------------------
// Single fused kernel. Inline per-warp parameter prep (no second launch),
// R=4 rows in flight per warp, lane l owns feature pair (2l, 2l+1).
// Hot loop has ZERO bounds predicates: the loop condition guarantees all R
// rows valid; a generic guarded tail handles any remainder (never taken for
// the benchmark shape).
// ---------------------------------------------------------------------------
__global__ void __launch_bounds__(256, 2)
qkan_kernel(const float* __restrict__ X, const float* __restrict__ w,
            const float* __restrict__ kc, float* __restrict__ out, int Btot) {
    const int lane = threadIdx.x & 31;
    const int warp = ((blockIdx.x * blockDim.x) + threadIdx.x) >> 5;
    const int nw = (gridDim.x * blockDim.x) >> 5;
    const int stride = nw * R;

    // ---- inline prep: lane l handles features f0=2l, f1=2l+1 ----
    u64 W[DEG];
    u64 C[KDEG + 1];
    {
        const int f0 = 2 * lane, f1 = f0 + 1;
        const float4* w4 = reinterpret_cast<const float4*>(w);
        float w0[DEG], w1[DEG];
#pragma unroll
        for (int i = 0; i < 4; i++) {
            float4 a = __ldg(&w4[f0 * 4 + i]);
            float4 b = __ldg(&w4[f1 * 4 + i]);
            w0[4 * i + 0] = a.x; w0[4 * i + 1] = a.y; w0[4 * i + 2] = a.z; w0[4 * i + 3] = a.w;
            w1[4 * i + 0] = b.x; w1[4 * i + 1] = b.y; w1[4 * i + 2] = b.z; w1[4 * i + 3] = b.w;
        }
        float d0 = 0.f, d1 = 0.f;
#pragma unroll
        for (int k = 0; k < DEG; k++) { d0 += fabsf(w0[k]); d1 += fabsf(w1[k]); }
        const float i0 = 1.f / d0, i1 = 1.f / d1;
#pragma unroll
        for (int k = 1; k <= DEG; k++) {
            int m = k & 3;
            float sg = (m == 1 || m == 2) ? 1.f : -1.f;
            W[k - 1] = pk2(sg * w0[k - 1] * i0, sg * w1[k - 1] * i1);
        }
        const float2* kc2 = reinterpret_cast<const float2*>(kc);
        float c0[KDEG + 1], c1[KDEG + 1];
#pragma unroll
        for (int i = 0; i < 3; i++) {
            float2 a = __ldg(&kc2[f0 * 3 + i]);
            float2 b = __ldg(&kc2[f1 * 3 + i]);
            c0[2 * i] = a.x; c0[2 * i + 1] = a.y;
            c1[2 * i] = b.x; c1[2 * i + 1] = b.y;
        }
#pragma unroll
        for (int j = 0; j <= KDEG; j++) {
            int m = j & 3;
            float sg = (j <= 2) ? 1.f : ((m == 1 || m == 2) ? 1.f : -1.f);
            C[j] = pk2(sg * c0[j], sg * c1[j]);
        }
    }

    const float2* __restrict__ X2 = reinterpret_cast<const float2*>(X);

    int b = warp * R;
    float2 xv[R];
    if (b + R <= Btot) {
#pragma unroll
        for (int r = 0; r < R; r++)
            xv[r] = __ldg(&X2[(size_t)(b + r) * (FNUM / 2) + lane]);
    }

    // ---- hot loop: no per-row predicates anywhere ----
    while (b + R <= Btot) {
        float2 cx[R];
#pragma unroll
        for (int r = 0; r < R; r++) cx[r] = xv[r];
        const int bn = b + stride;
        if (bn + R <= Btot) {                 // single predicate for prefetch
#pragma unroll
            for (int r = 0; r < R; r++)
                xv[r] = __ldg(&X2[(size_t)(bn + r) * (FNUM / 2) + lane]);
        }

        float s[R];
        body(cx, W, C, s);

        if (lane == 0) {
#pragma unroll
            for (int r = 0; r < R; r++) out[b + r] = s[r];
        }
        b = bn;
    }

    // ---- generic tail (never taken when Btot % R == 0 per warp coverage) ----
    if (b < Btot) {
        float2 cx[R];
#pragma unroll
        for (int r = 0; r < R; r++)
            cx[r] = (b + r < Btot) ? __ldg(&X2[(size_t)(b + r) * (FNUM / 2) + lane])
                                   : make_float2(0.f, 0.f);
        float s[R];
        body(cx, W, C, s);
        if (lane == 0) {
#pragma unroll
            for (int r = 0; r < R; r++)
                if (b + r < Btot) out[b + r] = s[r];
        }
    }
}

extern "C" void kernel_launch(void* const* d_in, const int* in_sizes, int n_in,
                              void* d_out, int out_size) {
    const float* X  = (const float*)d_in[0];
    const float* w  = (const float*)d_in[1];
    const float* kc = (const float*)d_in[2];
    float* out = (float*)d_out;
    int Btot = in_sizes[0] / FNUM;

    // Single fused launch: 2 blocks per SM (148 SMs), 8 warps each,
    // 4 rows in flight per warp.
    qkan_kernel<<<296, 256>>>(X, w, kc, out, Btot);
}

// round 13
// speedup vs baseline: 1.5940x; 1.5940x over previous
#include <cuda_runtime.h>
#include <cstdint>

#define FNUM 64
#define DEG 16
#define KDEG 5
#define R 4   // rows (batch elements) in flight per warp

// ---------------------------------------------------------------------------
// Packed f32x2 helpers (Blackwell fma.rn.f32x2 — PTX only, ptxas won't fuse)
// ---------------------------------------------------------------------------
typedef unsigned long long u64;

__device__ __forceinline__ u64 pk2(float a, float b) {
    u64 r; asm("mov.b64 %0,{%1,%2};" : "=l"(r) : "f"(a), "f"(b)); return r;
}
__device__ __forceinline__ float2 unpk2(u64 v) {
    float2 r; asm("mov.b64 {%0,%1},%2;" : "=f"(r.x), "=f"(r.y) : "l"(v)); return r;
}
__device__ __forceinline__ u64 ffma2(u64 a, u64 b, u64 c) {
    u64 d; asm("fma.rn.f32x2 %0,%1,%2,%3;" : "=l"(d) : "l"(a), "l"(b), "l"(c)); return d;
}
__device__ __forceinline__ u64 fadd2(u64 a, u64 b) {
    u64 d; asm("add.rn.f32x2 %0,%1,%2;" : "=l"(d) : "l"(a), "l"(b)); return d;
}
__device__ __forceinline__ u64 fmul2(u64 a, u64 b) {
    u64 d; asm("mul.rn.f32x2 %0,%1,%2;" : "=l"(d) : "l"(a), "l"(b)); return d;
}

#define SGN_  0x8000000080000000ULL  // packed sign-flip mask
#define MONE_ 0xBF800000BF800000ULL  // packed (-1.0f, -1.0f)

// ---------------------------------------------------------------------------
// Single kernel. Per-BLOCK prep into shared memory (threads 0..63, one
// feature each: L1-normalize LCU weights, fold the alternating-multiplier
// sign pattern, layout so lane l reads feature pair (2l, 2l+1) as one
// LDS.64). The hot loop keeps only row state in registers — parameters are
// re-read from smem each iteration (conflict-free, latency hidden by 4
// independent FFMA2 chains). This kills the local-memory demotion of the
// W/C register arrays that inflated L1 to 24% and allows 3 blocks/SM.
// ---------------------------------------------------------------------------
__global__ void __launch_bounds__(256, 3)
qkan_kernel(const float* __restrict__ X, const float* __restrict__ w,
            const float* __restrict__ kc, float* __restrict__ out, int Btot) {
    __shared__ float sW[DEG][FNUM];       // sigma_k * w[f][k] / sum|w[f][:]|
    __shared__ float sC[KDEG + 1][FNUM];  // sigma_j * c[f][j]

    const int tid = threadIdx.x;

    // ---- block-level prep: one feature per thread (threads 0..63) ----
    if (tid < FNUM) {
        const int f = tid;
        float wv[DEG];
        float den = 0.f;
#pragma unroll
        for (int k = 0; k < DEG; k++) { wv[k] = w[f * DEG + k]; den += fabsf(wv[k]); }
        const float inv = 1.f / den;
#pragma unroll
        for (int k = 1; k <= DEG; k++) {
            int m = k & 3;
            float sg = (m == 1 || m == 2) ? 1.f : -1.f;
            sW[k - 1][f] = sg * wv[k - 1] * inv;
        }
#pragma unroll
        for (int j = 0; j <= KDEG; j++) {
            int m = j & 3;
            float sg = (j <= 2) ? 1.f : ((m == 1 || m == 2) ? 1.f : -1.f);
            sC[j][f] = sg * kc[f * (KDEG + 1) + j];
        }
    }
    __syncthreads();

    const int lane = tid & 31;
    const int warp = ((blockIdx.x * blockDim.x) + tid) >> 5;
    const int nw = (gridDim.x * blockDim.x) >> 5;
    const int stride = nw * R;

    // packed-param views: entry [k*32 + lane] = (param[k][2*lane], param[k][2*lane+1])
    const u64* __restrict__ swq = reinterpret_cast<const u64*>(&sW[0][0]);
    const u64* __restrict__ scq = reinterpret_cast<const u64*>(&sC[0][0]);
    const float2* __restrict__ X2 = reinterpret_cast<const float2*>(X);

    int b = warp * R;
    float2 xv[R];
    if (b + R <= Btot) {
#pragma unroll
        for (int r = 0; r < R; r++)
            xv[r] = __ldg(&X2[(size_t)(b + r) * (FNUM / 2) + lane]);
    }

    // ---- hot loop: no per-row predicates ----
    while (b + R <= Btot) {
        float2 cx[R];
#pragma unroll
        for (int r = 0; r < R; r++) cx[r] = xv[r];
        const int bn = b + stride;
        if (bn + R <= Btot) {                 // single predicate for prefetch
#pragma unroll
            for (int r = 0; r < R; r++)
                xv[r] = __ldg(&X2[(size_t)(bn + r) * (FNUM / 2) + lane]);
        }

        u64 x2[R], nx2[R], um1[R], u[R], acc[R];
        u64 P;
        // ---- QSVT/LCU: sum_k w'_k * sigma_k T_k(x), k = 1..16 ----
#pragma unroll
        for (int r = 0; r < R; r++) {
            u64 x  = pk2(cx[r].x, cx[r].y);
            x2[r]  = fadd2(x, x);
            nx2[r] = x2[r] ^ SGN_;
            um1[r] = x;                        // u1 = T1
            u[r]   = ffma2(x2[r], x, MONE_);   // u2 = T2
        }
        P = swq[0 * 32 + lane];
#pragma unroll
        for (int r = 0; r < R; r++) acc[r] = fmul2(P, um1[r]);
        P = swq[1 * 32 + lane];
#pragma unroll
        for (int r = 0; r < R; r++) acc[r] = ffma2(P, u[r], acc[r]);
#pragma unroll
        for (int k = 3; k <= DEG; k++) {
#pragma unroll
            for (int r = 0; r < R; r++) {
                u64 un = ffma2((k & 1) ? nx2[r] : x2[r], u[r], um1[r]);
                um1[r] = u[r]; u[r] = un;
            }
            P = swq[(k - 1) * 32 + lane];
#pragma unroll
            for (int r = 0; r < R; r++) acc[r] = ffma2(P, u[r], acc[r]);
        }

        // ---- tanh: z = 1 - 2/(e^{2f}+1); |feat| <= 1 so always accurate ----
        u64 z[R];
#pragma unroll
        for (int r = 0; r < R; r++) {
            float2 fe = unpk2(acc[r]);
            float e0 = __expf(2.f * fe.x);
            float e1 = __expf(2.f * fe.y);
            float z0 = 1.f - __fdividef(2.f, e0 + 1.f);
            float z1 = 1.f - __fdividef(2.f, e1 + 1.f);
            z[r] = pk2(z0, z1);
        }

        // ---- KAN: sum_j c'_j * sigma_j T_j(z), j = 0..5 ----
        u64 kacc[R];
#pragma unroll
        for (int r = 0; r < R; r++) {
            x2[r]  = fadd2(z[r], z[r]);
            nx2[r] = x2[r] ^ SGN_;
            um1[r] = z[r];
            u[r]   = ffma2(x2[r], z[r], MONE_);  // T2
        }
        {
            u64 C0 = scq[0 * 32 + lane];
            u64 C1 = scq[1 * 32 + lane];
#pragma unroll
            for (int r = 0; r < R; r++) kacc[r] = ffma2(C1, um1[r], C0);
        }
        P = scq[2 * 32 + lane];
#pragma unroll
        for (int r = 0; r < R; r++) kacc[r] = ffma2(P, u[r], kacc[r]);
#pragma unroll
        for (int j = 3; j <= KDEG; j++) {
#pragma unroll
            for (int r = 0; r < R; r++) {
                u64 un = ffma2((j & 1) ? nx2[r] : x2[r], u[r], um1[r]);
                um1[r] = u[r]; u[r] = un;
            }
            P = scq[j * 32 + lane];
#pragma unroll
            for (int r = 0; r < R; r++) kacc[r] = ffma2(P, u[r], kacc[r]);
        }

        // ---- reduce 64 features: 2 per lane + 5-level butterfly (R-wide) ----
        float s[R];
#pragma unroll
        for (int r = 0; r < R; r++) {
            float2 pr = unpk2(kacc[r]);
            s[r] = pr.x + pr.y;
        }
#pragma unroll
        for (int o = 16; o; o >>= 1)
#pragma unroll
            for (int r = 0; r < R; r++)
                s[r] += __shfl_xor_sync(0xffffffffu, s[r], o);
        if (lane == 0) {
#pragma unroll
            for (int r = 0; r < R; r++) out[b + r] = s[r];
        }
        b = bn;
    }

    // ---- tail: clamped indices, guarded stores (never taken when Btot%R==0) ----
    if (b < Btot) {
        float2 cx[R];
#pragma unroll
        for (int r = 0; r < R; r++) {
            int ri = (b + r < Btot) ? (b + r) : (Btot - 1);
            cx[r] = __ldg(&X2[(size_t)ri * (FNUM / 2) + lane]);
        }

        u64 x2[R], nx2[R], um1[R], u[R], acc[R];
        u64 P;
#pragma unroll
        for (int r = 0; r < R; r++) {
            u64 x  = pk2(cx[r].x, cx[r].y);
            x2[r]  = fadd2(x, x);
            nx2[r] = x2[r] ^ SGN_;
            um1[r] = x;
            u[r]   = ffma2(x2[r], x, MONE_);
        }
        P = swq[0 * 32 + lane];
#pragma unroll
        for (int r = 0; r < R; r++) acc[r] = fmul2(P, um1[r]);
        P = swq[1 * 32 + lane];
#pragma unroll
        for (int r = 0; r < R; r++) acc[r] = ffma2(P, u[r], acc[r]);
#pragma unroll
        for (int k = 3; k <= DEG; k++) {
#pragma unroll
            for (int r = 0; r < R; r++) {
                u64 un = ffma2((k & 1) ? nx2[r] : x2[r], u[r], um1[r]);
                um1[r] = u[r]; u[r] = un;
            }
            P = swq[(k - 1) * 32 + lane];
#pragma unroll
            for (int r = 0; r < R; r++) acc[r] = ffma2(P, u[r], acc[r]);
        }
        u64 z[R];
#pragma unroll
        for (int r = 0; r < R; r++) {
            float2 fe = unpk2(acc[r]);
            float e0 = __expf(2.f * fe.x);
            float e1 = __expf(2.f * fe.y);
            z[r] = pk2(1.f - __fdividef(2.f, e0 + 1.f),
                       1.f - __fdividef(2.f, e1 + 1.f));
        }
        u64 kacc[R];
#pragma unroll
        for (int r = 0; r < R; r++) {
            x2[r]  = fadd2(z[r], z[r]);
            nx2[r] = x2[r] ^ SGN_;
            um1[r] = z[r];
            u[r]   = ffma2(x2[r], z[r], MONE_);
        }
        {
            u64 C0 = scq[0 * 32 + lane];
            u64 C1 = scq[1 * 32 + lane];
#pragma unroll
            for (int r = 0; r < R; r++) kacc[r] = ffma2(C1, um1[r], C0);
        }
        P = scq[2 * 32 + lane];
#pragma unroll
        for (int r = 0; r < R; r++) kacc[r] = ffma2(P, u[r], kacc[r]);
#pragma unroll
        for (int j = 3; j <= KDEG; j++) {
#pragma unroll
            for (int r = 0; r < R; r++) {
                u64 un = ffma2((j & 1) ? nx2[r] : x2[r], u[r], um1[r]);
                um1[r] = u[r]; u[r] = un;
            }
            P = scq[j * 32 + lane];
#pragma unroll
            for (int r = 0; r < R; r++) kacc[r] = ffma2(P, u[r], kacc[r]);
        }
        float s[R];
#pragma unroll
        for (int r = 0; r < R; r++) {
            float2 pr = unpk2(kacc[r]);
            s[r] = pr.x + pr.y;
        }
#pragma unroll
        for (int o = 16; o; o >>= 1)
#pragma unroll
            for (int r = 0; r < R; r++)
                s[r] += __shfl_xor_sync(0xffffffffu, s[r], o);
        if (lane == 0) {
#pragma unroll
            for (int r = 0; r < R; r++)
                if (b + r < Btot) out[b + r] = s[r];
        }
    }
}

extern "C" void kernel_launch(void* const* d_in, const int* in_sizes, int n_in,
                              void* d_out, int out_size) {
    const float* X  = (const float*)d_in[0];
    const float* w  = (const float*)d_in[1];
    const float* kc = (const float*)d_in[2];
    float* out = (float*)d_out;
    int Btot = in_sizes[0] / FNUM;

    // Single launch: 3 blocks per SM (148 SMs), 8 warps each,
    // 4 rows in flight per warp, params in shared memory.
    qkan_kernel<<<444, 256>>>(X, w, kc, out, Btot);
}